// round 7
// baseline (speedup 1.0000x reference)
#include <cuda_runtime.h>

// YOLO loss, sm_103a — round 6: gather-free algebraic reformulation.
//
// Per cell:  Σ_t coord = Σ_k [ n·p_k² − 2·p_k·S1_k + S2_k ]           (k = cx,cy,w,h)
//            Σ_t class = n·Σ_c p_c²  − 2·Σ_t p_{cls_t}  + n
//            noobj     = 0.5·( conf0²·[n==0] + conf1² + conf2² )
// => per-(b,cell) aggregates {n, S1} from a tiny target scatter, then a fully
// coalesced float4 stream over 87 channels; only Σ_t p_{cls_t} stays a gather
// (50 loads/image). No dedup needed: obj == (n>0).

#define S_GRID   26
#define NCH      255
#define CELLS    676
#define Q4       169              // CELLS/4
#define BATCH_N  128
#define T_TGT    50
#define L_COORD  5.0f
#define L_NOOBJ  0.5f

#define SLICES   8                // channel slices per image
#define NBLOCKS  (BATCH_N * SLICES)   // 1024
#define NIDX     87               // used channels: 0..84, 85, 170

__device__ float    g_acc = 0.0f;     // reset by last block each call
__device__ unsigned g_cnt = 0u;

__global__ __launch_bounds__(256)
void yolo_loss_kernel(const float* __restrict__ pred,
                      const float* __restrict__ tgt,
                      float* __restrict__ out)
{
    const int tid = threadIdx.x;
    const int b   = blockIdx.x >> 3;       // image
    const int r   = blockIdx.x & 7;        // channel slice

    __shared__ float4 s_n4[Q4];            // per-cell valid-target count
    __shared__ float4 s_s14[4][Q4];        // per-cell coord sums S1_k
    __shared__ float  s_warp[8];

    // ---- phase A: zero + scatter targets into per-cell aggregates ----
    for (int i = tid; i < Q4; i += 256) {
        s_n4[i] = make_float4(0.f, 0.f, 0.f, 0.f);
        #pragma unroll
        for (int k = 0; k < 4; k++)
            s_s14[k][i] = make_float4(0.f, 0.f, 0.f, 0.f);
    }
    __syncthreads();

    float sum = 0.0f;

    const float* tgb = tgt + (size_t)b * T_TGT * 5;
    if (tid < T_TGT) {
        const float clsf = __ldg(tgb + tid * 5 + 0);
        const float cx   = __ldg(tgb + tid * 5 + 1);
        const float cy   = __ldg(tgb + tid * 5 + 2);
        const float tw   = __ldg(tgb + tid * 5 + 3);
        const float th   = __ldg(tgb + tid * 5 + 4);
        const int gx = (int)(cx * S_GRID);     // trunc == floor (cx >= 0)
        const int gy = (int)(cy * S_GRID);
        if (gx < S_GRID && gy < S_GRID) {
            const int cell = min(max(gy,0),S_GRID-1) * S_GRID
                           + min(max(gx,0),S_GRID-1);
            atomicAdd(&((float*)s_n4)[cell], 1.0f);
            atomicAdd(&((float*)s_s14[0])[cell], cx);
            atomicAdd(&((float*)s_s14[1])[cell], cy);
            atomicAdd(&((float*)s_s14[2])[cell], tw);
            atomicAdd(&((float*)s_s14[3])[cell], th);
            if (r == 0) {
                // target-side constants: +1 (one-hot²) + 5·S2 (coord squares)
                sum += 1.0f + L_COORD * (cx*cx + cy*cy + tw*tw + th*th);
                // the single remaining gather: -2·p[cls channel, cell]
                const int clsi = (int)clsf;
                const float pg = __ldg(pred + ((size_t)b * NCH + 5 + clsi) * CELLS + cell);
                sum -= 2.0f * pg;
            }
        }
    }
    __syncthreads();

    // ---- phase B: coalesced float4 stream over this slice's channels ----
    const int nidx  = (NIDX - r + SLICES - 1) / SLICES;    // 11 or 10
    const int items = nidx * Q4;
    for (int i = tid; i < items; i += 256) {
        const int ii  = i / Q4;
        const int j   = i - ii * Q4;
        const int idx = r + SLICES * ii;                    // 0..86
        const int c   = (idx < 85) ? idx : ((idx == 85) ? 85 : 170);

        const float4 p = __ldg((const float4*)(pred
                          + ((size_t)b * NCH + c) * CELLS) + j);

        if (idx == 0) {
            // box-0 confidence: counts only where no object
            const float4 nv = s_n4[j];
            float t0 = 0.f;
            if (nv.x == 0.f) t0 += p.x * p.x;
            if (nv.y == 0.f) t0 += p.y * p.y;
            if (nv.z == 0.f) t0 += p.z * p.z;
            if (nv.w == 0.f) t0 += p.w * p.w;
            sum += L_NOOBJ * t0;
        } else if (idx <= 4) {
            // coord channel k: 5·(n·p² − 2·p·S1)
            const float4 nv = s_n4[j];
            const float4 s1 = s_s14[idx - 1][j];
            float t0 = p.x * (nv.x * p.x - 2.f * s1.x)
                     + p.y * (nv.y * p.y - 2.f * s1.y)
                     + p.z * (nv.z * p.z - 2.f * s1.z)
                     + p.w * (nv.w * p.w - 2.f * s1.w);
            sum += L_COORD * t0;
        } else if (idx < 85) {
            // class channel: n·p²
            const float4 nv = s_n4[j];
            sum += nv.x * p.x * p.x + nv.y * p.y * p.y
                 + nv.z * p.z * p.z + nv.w * p.w * p.w;
        } else {
            // boxes 1,2 confidence: always no-object
            sum += L_NOOBJ * (p.x*p.x + p.y*p.y + p.z*p.z + p.w*p.w);
        }
    }

    // ---- block reduce + last-block-done finalization (single launch) ----
    const int lane = tid & 31;
    const int warp = tid >> 5;
    #pragma unroll
    for (int off = 16; off; off >>= 1)
        sum += __shfl_down_sync(0xffffffffu, sum, off);
    if (lane == 0) s_warp[warp] = sum;
    __syncthreads();
    if (tid == 0) {
        float v = s_warp[0];
        #pragma unroll
        for (int w = 1; w < 8; w++) v += s_warp[w];
        atomicAdd(&g_acc, v);
        __threadfence();
        const unsigned ticket = atomicAdd(&g_cnt, 1u);
        if (ticket == NBLOCKS - 1) {
            const float total = atomicAdd(&g_acc, 0.0f);   // coherent read
            out[0] = total * (1.0f / BATCH_N);
            g_acc = 0.0f;                                  // replay-safe reset
            g_cnt = 0u;
        }
    }
}

extern "C" void kernel_launch(void* const* d_in, const int* in_sizes, int n_in,
                              void* d_out, int out_size)
{
    const float* pred = (const float*)d_in[0];
    const float* tgt  = (const float*)d_in[1];
    float* out = (float*)d_out;

    yolo_loss_kernel<<<NBLOCKS, 256>>>(pred, tgt, out);
}

// round 9
// speedup vs baseline: 1.1950x; 1.1950x over previous
#include <cuda_runtime.h>

// YOLO loss, sm_103a — round 7: lean hybrid.
//   target-side (50 thr/img): coord gathers + cls gather:  5·Σd² + 1 − 2·p_cls
//   stream (169 thr/slice):   class channels  n·Σ_c p_c²   (fixed j, unrolled 20)
//                             conf channels   0.5·conf²    (conf0 masked by n==0)
//   per-cell n via 50 shared atomics; no dedup, no S1/S2, no divisions in hot loop.

#define S_GRID   26
#define NCH      255
#define CELLS    676
#define Q4       169               // CELLS/4
#define BATCH_N  128
#define T_TGT    50
#define L_COORD  5.0f
#define L_NOOBJ  0.5f

#define CSPLIT   4                 // class-channel slices per image (20 ch each)
#define TPB      192
#define NBLOCKS  (BATCH_N * CSPLIT)    // 512

__device__ float    g_acc = 0.0f;      // reset by last block each call
__device__ unsigned g_cnt = 0u;

__global__ __launch_bounds__(TPB)
void yolo_loss_kernel(const float* __restrict__ pred,
                      const float* __restrict__ tgt,
                      float* __restrict__ out)
{
    const int tid = threadIdx.x;
    const int b   = blockIdx.x >> 2;       // image
    const int r   = blockIdx.x & 3;        // slice

    __shared__ float s_n[CELLS];
    __shared__ float s_warp[TPB / 32];

    // ---- phase A: per-cell valid-target count (n) ----
    for (int i = tid; i < CELLS; i += TPB) s_n[i] = 0.0f;
    __syncthreads();
    const float* tgb = tgt + (size_t)b * T_TGT * 5;
    if (tid < T_TGT) {
        const float cx = __ldg(tgb + tid * 5 + 1);
        const float cy = __ldg(tgb + tid * 5 + 2);
        const int gx = (int)(cx * S_GRID);      // trunc == floor (cx >= 0)
        const int gy = (int)(cy * S_GRID);
        if (gx < S_GRID && gy < S_GRID) {
            const int cell = min(max(gy,0),S_GRID-1) * S_GRID
                           + min(max(gx,0),S_GRID-1);
            atomicAdd(&s_n[cell], 1.0f);
        }
    }
    __syncthreads();

    float sum = 0.0f;
    const float* pb = pred + (size_t)b * NCH * CELLS;

    if (tid < Q4) {
        const int j = tid;                      // this thread's float4 column
        // ---- class-channel stream: 20 channels, fixed j, nv once ----
        const float4* base = (const float4*)(pb + (size_t)(5 + 20 * r) * CELLS) + j;
        float4 s = make_float4(0.f, 0.f, 0.f, 0.f);
        #pragma unroll
        for (int k = 0; k < 20; k++) {
            const float4 p = __ldg(base + k * Q4);
            s.x = fmaf(p.x, p.x, s.x);
            s.y = fmaf(p.y, p.y, s.y);
            s.z = fmaf(p.z, p.z, s.z);
            s.w = fmaf(p.w, p.w, s.w);
        }
        const float4 nv = *(const float4*)&s_n[4 * j];
        sum = nv.x * s.x + nv.y * s.y + nv.z * s.z + nv.w * s.w;

        // ---- conf channel duty ----
        if (r == 0) {                           // conf0, masked by n==0
            const float4 p = __ldg((const float4*)pb + j);
            float t = 0.f;
            t += (nv.x == 0.f) ? p.x * p.x : 0.f;
            t += (nv.y == 0.f) ? p.y * p.y : 0.f;
            t += (nv.z == 0.f) ? p.z * p.z : 0.f;
            t += (nv.w == 0.f) ? p.w * p.w : 0.f;
            sum += L_NOOBJ * t;
        } else if (r == 1) {                    // conf of box 1 (ch 85)
            const float4 p = __ldg((const float4*)(pb + (size_t)85 * CELLS) + j);
            sum += L_NOOBJ * (p.x*p.x + p.y*p.y + p.z*p.z + p.w*p.w);
        } else if (r == 2) {                    // conf of box 2 (ch 170)
            const float4 p = __ldg((const float4*)(pb + (size_t)170 * CELLS) + j);
            sum += L_NOOBJ * (p.x*p.x + p.y*p.y + p.z*p.z + p.w*p.w);
        }
    }

    // ---- target-side term (slice 3 only): coord + cls gather ----
    if (r == 3 && tid < T_TGT) {
        const float clsf = __ldg(tgb + tid * 5 + 0);
        const float cx   = __ldg(tgb + tid * 5 + 1);
        const float cy   = __ldg(tgb + tid * 5 + 2);
        const float tw   = __ldg(tgb + tid * 5 + 3);
        const float th   = __ldg(tgb + tid * 5 + 4);
        const int gx = (int)(cx * S_GRID);
        const int gy = (int)(cy * S_GRID);
        if (gx < S_GRID && gy < S_GRID) {
            const int cell = min(max(gy,0),S_GRID-1) * S_GRID
                           + min(max(gx,0),S_GRID-1);
            const float* cp = pb + cell;
            const int clsi = (int)clsf;
            const float p1 = __ldg(cp + (size_t)1 * CELLS);
            const float p2 = __ldg(cp + (size_t)2 * CELLS);
            const float p3 = __ldg(cp + (size_t)3 * CELLS);
            const float p4 = __ldg(cp + (size_t)4 * CELLS);
            const float pg = __ldg(cp + (size_t)(5 + clsi) * CELLS);
            const float d1 = p1 - cx, d2 = p2 - cy, d3 = p3 - tw, d4 = p4 - th;
            sum += L_COORD * (d1*d1 + d2*d2 + d3*d3 + d4*d4) + 1.0f - 2.0f * pg;
        }
    }

    // ---- block reduce + last-block-done finalization (single launch) ----
    const int lane = tid & 31;
    const int warp = tid >> 5;
    #pragma unroll
    for (int off = 16; off; off >>= 1)
        sum += __shfl_down_sync(0xffffffffu, sum, off);
    if (lane == 0) s_warp[warp] = sum;
    __syncthreads();
    if (tid == 0) {
        float v = s_warp[0];
        #pragma unroll
        for (int w = 1; w < TPB / 32; w++) v += s_warp[w];
        atomicAdd(&g_acc, v);
        __threadfence();
        const unsigned ticket = atomicAdd(&g_cnt, 1u);
        if (ticket == NBLOCKS - 1) {
            const float total = atomicAdd(&g_acc, 0.0f);   // coherent read
            out[0] = total * (1.0f / BATCH_N);
            g_acc = 0.0f;                                  // replay-safe reset
            g_cnt = 0u;
        }
    }
}

extern "C" void kernel_launch(void* const* d_in, const int* in_sizes, int n_in,
                              void* d_out, int out_size)
{
    const float* pred = (const float*)d_in[0];
    const float* tgt  = (const float*)d_in[1];
    float* out = (float*)d_out;

    yolo_loss_kernel<<<NBLOCKS, TPB>>>(pred, tgt, out);
}